// round 14
// baseline (speedup 1.0000x reference)
#include <cuda_runtime.h>
#include <math.h>
#include <stdint.h>

// Problem constants (fixed-shape problem)
#define NN 40000      // nodes
#define NE 150000     // edges per type
#define HH 4          // heads
#define DD 128        // per-head dim
#define FF 512        // HH*DD
#define FF2 1024      // both edge types concatenated
#define NOUT 2983
#define NOUTP 2984    // padded (16B-aligned rows for cp.async)

// ---------------------------------------------------------------------------
// Scratch (device globals; no allocation allowed)
// ---------------------------------------------------------------------------
__device__ float g_feat[(size_t)NN * FF2];           // both types per layer
__device__ float g_h1  [(size_t)NN * FF];
__device__ float g_h2  [(size_t)NN * FF];
__device__ float g_xc  [(size_t)NN * 1024];          // tf32-rounded x
__device__ float g_w0  [1024 * FF2];                 // concat [K,1024] tf32
__device__ float g_w1  [512 * FF2];
__device__ float g_w2  [512 * FF2];
__device__ float g_wo  [FF * NOUTP];                 // tf32, padded Wout
__device__ float g_el  [2][NN * HH];                 // per edge type
__device__ float g_er  [2][NN * HH];
__device__ int   g_deg [NN];
__device__ int   g_cur [NN];
__device__ int   g_rp  [2][NN + 1];
__device__ int   g_csrc[2][NE];

// ---------------------------------------------------------------------------
// Helpers
// ---------------------------------------------------------------------------
__device__ __forceinline__ float to_tf32(float x)
{
    unsigned r;
    asm("cvt.rna.tf32.f32 %0, %1;" : "=r"(r) : "f"(x));
    return __uint_as_float(r);
}

__device__ __forceinline__ void mma_tf32(float c[4],
                                         float a0, float a1, float a2, float a3,
                                         float b0, float b1)
{
    asm volatile(
        "mma.sync.aligned.m16n8k8.row.col.f32.tf32.tf32.f32 "
        "{%0,%1,%2,%3}, {%4,%5,%6,%7}, {%8,%9}, {%0,%1,%2,%3};\n"
        : "+f"(c[0]), "+f"(c[1]), "+f"(c[2]), "+f"(c[3])
        : "r"(__float_as_uint(a0)), "r"(__float_as_uint(a1)),
          "r"(__float_as_uint(a2)), "r"(__float_as_uint(a3)),
          "r"(__float_as_uint(b0)), "r"(__float_as_uint(b1)));
}

__device__ __forceinline__ void cp_async16(uint32_t saddr, const void* gptr, int bytes)
{
    asm volatile("cp.async.cg.shared.global [%0], [%1], 16, %2;\n"
                 :: "r"(saddr), "l"(gptr), "r"(bytes));
}
__device__ __forceinline__ void cp_commit()
{
    asm volatile("cp.async.commit_group;\n");
}
__device__ __forceinline__ void cp_wait1()
{
    asm volatile("cp.async.wait_group 1;\n" ::: "memory");
}

// ---------------------------------------------------------------------------
// TF32 tensor-core GEMM, cp.async 3-stage pipeline, 2 CTAs/SM.
// CTA tile 128x128, BK=32, 256 threads (8 warps), warp tile 64x32.
// C[M,Ncols] = A[M,K] @ B[K,NB] (row-major), Ncols <= NB.
// (identical to the measured 2480us configuration)
// ---------------------------------------------------------------------------
#define BM 128
#define BN 128
#define BKK 32
#define STAGES 3
#define AS_LD 36
#define BS_LD 136
#define A_FLOATS (BM * AS_LD)                 // 4608
#define B_FLOATS (BKK * BS_LD)                // 4352
#define STG_FLOATS (A_FLOATS + B_FLOATS)      // 8960
#define SMEM_BYTES (STAGES * STG_FLOATS * 4)  // 107520 -> 2 CTAs/SM

extern __shared__ float smem_dyn[];

template <bool ADD_BIAS>
__global__ __launch_bounds__(256, 2)
void gemm_pipe(const float* __restrict__ A, const float* __restrict__ B,
               float* __restrict__ C, int M, int Ncols, int NB, int K,
               const float* __restrict__ bias)
{
    const int tid  = threadIdx.x;
    const int wid  = tid >> 5;
    const int lane = tid & 31;
    const int wm   = wid & 1;          // 2 row groups x 64
    const int wn   = wid >> 1;         // 4 col groups x 32
    const int g    = lane >> 2;
    const int q    = lane & 3;

    const int bm = blockIdx.y * BM;
    const int bn = blockIdx.x * BN;

    const uint32_t sbase = (uint32_t)__cvta_generic_to_shared(smem_dyn);

    float c[4][4][4];
    #pragma unroll
    for (int i = 0; i < 4; i++)
        #pragma unroll
        for (int j = 0; j < 4; j++)
            #pragma unroll
            for (int r = 0; r < 4; r++) c[i][j][r] = 0.f;

    const int nt = K / BKK;

    auto load_stage = [&](int s, int t) {
        const int k0 = t * BKK;
        const uint32_t ss = sbase + (uint32_t)(s * STG_FLOATS) * 4u;
        #pragma unroll
        for (int i = 0; i < 4; i++) {
            int f   = i * 256 + tid;
            int row = f >> 3;                 // 0..127
            int kc  = (f & 7) * 4;            // 0..28
            int m   = bm + row;
            const float* ga = (m < M) ? (A + (size_t)m * K + k0 + kc) : A;
            cp_async16(ss + (uint32_t)(row * AS_LD + kc) * 4u, ga, (m < M) ? 16 : 0);
        }
        #pragma unroll
        for (int i = 0; i < 4; i++) {
            int f    = i * 256 + tid;
            int brow = f >> 5;                // 0..31
            int bcol = (f & 31) * 4;          // 0..124
            int n    = bn + bcol;
            int rem  = NB - n;
            int bytes = rem >= 4 ? 16 : (rem > 0 ? rem * 4 : 0);
            const float* gb = (bytes > 0) ? (B + (size_t)(k0 + brow) * NB + n) : B;
            cp_async16(ss + (uint32_t)(A_FLOATS + brow * BS_LD + bcol) * 4u, gb, bytes);
        }
        cp_commit();
    };

    #pragma unroll
    for (int s = 0; s < STAGES - 1; s++)
        load_stage(s, s);

    for (int t = 0; t < nt; t++) {
        cp_wait1();
        __syncthreads();

        const float* As = smem_dyn + (t % STAGES) * STG_FLOATS;
        const float* Bs = As + A_FLOATS;

        #pragma unroll
        for (int ks = 0; ks < 4; ks++) {
            const int kb = ks * 8;
            float a[4][4], b[4][2];
            #pragma unroll
            for (int mi = 0; mi < 4; mi++) {
                int r = wm * 64 + mi * 16 + g;
                a[mi][0] = As[(r    ) * AS_LD + kb + q];
                a[mi][1] = As[(r + 8) * AS_LD + kb + q];
                a[mi][2] = As[(r    ) * AS_LD + kb + q + 4];
                a[mi][3] = As[(r + 8) * AS_LD + kb + q + 4];
            }
            #pragma unroll
            for (int nj = 0; nj < 4; nj++) {
                int cn = wn * 32 + nj * 8 + g;
                b[nj][0] = Bs[(kb + q    ) * BS_LD + cn];
                b[nj][1] = Bs[(kb + q + 4) * BS_LD + cn];
            }
            #pragma unroll
            for (int mi = 0; mi < 4; mi++)
                #pragma unroll
                for (int nj = 0; nj < 4; nj++)
                    mma_tf32(c[mi][nj], a[mi][0], a[mi][1], a[mi][2], a[mi][3],
                             b[nj][0], b[nj][1]);
        }

        if (t + STAGES - 1 < nt)
            load_stage((t + STAGES - 1) % STAGES, t + STAGES - 1);
        else
            cp_commit();
    }

    #pragma unroll
    for (int mi = 0; mi < 4; mi++) {
        int row0 = bm + wm * 64 + mi * 16 + g;
        #pragma unroll
        for (int nj = 0; nj < 4; nj++) {
            int col0 = bn + wn * 32 + nj * 8 + 2 * q;
            #pragma unroll
            for (int r = 0; r < 4; r++) {
                int row = row0 + (r >= 2 ? 8 : 0);
                int col = col0 + (r & 1);
                if (row < M && col < Ncols) {
                    float v = c[mi][nj][r];
                    if (ADD_BIAS) v += bias[col];
                    C[(size_t)row * Ncols + col] = v;
                }
            }
        }
    }
}

// ---------------------------------------------------------------------------
// tf32 pre-rounding / weight concat converts
// ---------------------------------------------------------------------------
__global__ void cvt_kernel(const float* __restrict__ in, float* __restrict__ out, int n4)
{
    int i = blockIdx.x * blockDim.x + threadIdx.x;
    if (i >= n4) return;
    float4 v = reinterpret_cast<const float4*>(in)[i];
    v.x = to_tf32(v.x); v.y = to_tf32(v.y);
    v.z = to_tf32(v.z); v.w = to_tf32(v.w);
    reinterpret_cast<float4*>(out)[i] = v;
}

// in: [2, K, 512] -> out: [K, 1024] with cols [t*512 + n], tf32-rounded
__global__ void wcat_kernel(const float* __restrict__ in, float* __restrict__ out, int K)
{
    int i = blockIdx.x * blockDim.x + threadIdx.x;
    if (i >= K * FF2) return;
    int k = i >> 10;
    int c = i & 1023;
    int t = c >> 9;
    int n = c & 511;
    out[i] = to_tf32(in[((size_t)t * K + k) * 512 + n]);
}

__global__ void pad_wout_kernel(const float* __restrict__ w, float* __restrict__ o)
{
    int i = blockIdx.x * blockDim.x + threadIdx.x;
    if (i >= FF * NOUTP) return;
    int r = i / NOUTP, c = i - r * NOUTP;
    o[i] = (c < NOUT) ? to_tf32(w[r * NOUT + c]) : 0.f;
}

// ---------------------------------------------------------------------------
// CSR construction
// ---------------------------------------------------------------------------
__global__ void hist_kernel(const int* __restrict__ dst, int* __restrict__ deg)
{
    int i = blockIdx.x * blockDim.x + threadIdx.x;
    if (i < NE) atomicAdd(&deg[dst[i]], 1);
}

__global__ __launch_bounds__(1024)
void scan_kernel(const int* __restrict__ deg, int* __restrict__ rp,
                 int* __restrict__ cur)
{
    const int CH = 40;
    __shared__ int sm[1024];
    int tid = threadIdx.x;
    int start = tid * CH;

    int sum = 0;
    #pragma unroll 4
    for (int j = 0; j < CH; j++) {
        int i = start + j;
        if (i < NN) sum += deg[i];
    }
    sm[tid] = sum;
    __syncthreads();
    for (int off = 1; off < 1024; off <<= 1) {
        int t = (tid >= off) ? sm[tid - off] : 0;
        __syncthreads();
        sm[tid] += t;
        __syncthreads();
    }
    int run = sm[tid] - sum;
    for (int j = 0; j < CH; j++) {
        int i = start + j;
        if (i < NN) {
            rp[i]  = run;
            cur[i] = run;
            run += deg[i];
        }
    }
    if (tid == 1023) rp[NN] = sm[1023];
}

__global__ void scatter_kernel(const int* __restrict__ src, const int* __restrict__ dst,
                               int* __restrict__ cur, int* __restrict__ csrc)
{
    int i = blockIdx.x * blockDim.x + threadIdx.x;
    if (i < NE) {
        int p = atomicAdd(&cur[dst[i]], 1);
        csrc[p] = src[i];
    }
}

// ---------------------------------------------------------------------------
// Attention logits, BOTH edge types in one pass. One warp per (node, head).
// ---------------------------------------------------------------------------
__global__ void logits2_kernel(const float* __restrict__ feat,
                               const float* __restrict__ al,
                               const float* __restrict__ ar,
                               float* __restrict__ el, float* __restrict__ er)
{
    int gw   = (blockIdx.x * blockDim.x + threadIdx.x) >> 5;
    int lane = threadIdx.x & 31;
    if (gw >= NN * HH) return;
    int n = gw >> 2;
    int h = gw & 3;

    #pragma unroll
    for (int t = 0; t < 2; t++) {
        float4 fv = reinterpret_cast<const float4*>(feat + (size_t)n * FF2 + t * FF + h * DD)[lane];
        float4 av = reinterpret_cast<const float4*>(al + t * FF + h * DD)[lane];
        float4 rv = reinterpret_cast<const float4*>(ar + t * FF + h * DD)[lane];

        float dl = fv.x * av.x + fv.y * av.y + fv.z * av.z + fv.w * av.w;
        float dr = fv.x * rv.x + fv.y * rv.y + fv.z * rv.z + fv.w * rv.w;
        #pragma unroll
        for (int o = 16; o; o >>= 1) {
            dl += __shfl_xor_sync(0xFFFFFFFFu, dl, o);
            dr += __shfl_xor_sync(0xFFFFFFFFu, dr, o);
        }
        if (lane == 0) {
            el[t * (NN * HH) + gw] = dl;
            er[t * (NN * HH) + gw] = dr;
        }
    }
}

// ---------------------------------------------------------------------------
// Fused aggregation, BOTH edge types: per (dst,head) warp,
//   out = act(softmax-agg_t0 + b0) + act(softmax-agg_t1 + b1), tf32-rounded.
// ---------------------------------------------------------------------------
__global__ __launch_bounds__(256)
void aggr2_kernel(const int* __restrict__ rp0, const int* __restrict__ cs0,
                  const int* __restrict__ rp1, const int* __restrict__ cs1,
                  const float* __restrict__ el, const float* __restrict__ er,
                  const float* __restrict__ feat, const float* __restrict__ bias,
                  float* __restrict__ hout, int activate)
{
    int gw   = (blockIdx.x * blockDim.x + threadIdx.x) >> 5;
    int lane = threadIdx.x & 31;
    if (gw >= NN * HH) return;
    int n = gw >> 2;
    int h = gw & 3;

    float4 out4 = make_float4(0.f, 0.f, 0.f, 0.f);

    #pragma unroll
    for (int t = 0; t < 2; t++) {
        const int* rp = t ? rp1 : rp0;
        const int* cs = t ? cs1 : cs0;
        const float* elt = el + t * (NN * HH);
        float erd = er[t * (NN * HH) + gw];
        const float* ft = feat + t * FF;

        int beg = rp[n];
        int end = rp[n + 1];

        float mx = -INFINITY;
        for (int i = beg + lane; i < end; i += 32) {
            int s = cs[i];
            float v = elt[s * HH + h] + erd;
            v = (v > 0.f) ? v : 0.2f * v;
            mx = fmaxf(mx, v);
        }
        #pragma unroll
        for (int o = 16; o; o >>= 1)
            mx = fmaxf(mx, __shfl_xor_sync(0xFFFFFFFFu, mx, o));

        float ss = 0.f;
        for (int i = beg + lane; i < end; i += 32) {
            int s = cs[i];
            float v = elt[s * HH + h] + erd;
            v = (v > 0.f) ? v : 0.2f * v;
            ss += __expf(v - mx);
        }
        #pragma unroll
        for (int o = 16; o; o >>= 1)
            ss += __shfl_xor_sync(0xFFFFFFFFu, ss, o);
        float inv = (end > beg) ? 1.f / ss : 0.f;

        float4 acc = make_float4(0.f, 0.f, 0.f, 0.f);
        for (int i = beg; i < end; i++) {
            int s = cs[i];
            float v = elt[s * HH + h] + erd;
            v = (v > 0.f) ? v : 0.2f * v;
            float a = __expf(v - mx) * inv;
            float4 fv = reinterpret_cast<const float4*>(ft + (size_t)s * FF2 + h * DD)[lane];
            acc.x = fmaf(a, fv.x, acc.x);
            acc.y = fmaf(a, fv.y, acc.y);
            acc.z = fmaf(a, fv.z, acc.z);
            acc.w = fmaf(a, fv.w, acc.w);
        }

        float4 b4 = reinterpret_cast<const float4*>(bias + t * FF + h * DD)[lane];
        float o0 = acc.x + b4.x, o1 = acc.y + b4.y;
        float o2 = acc.z + b4.z, o3 = acc.w + b4.w;
        if (activate) {
            o0 = (o0 > 0.f) ? o0 : 0.01f * o0;
            o1 = (o1 > 0.f) ? o1 : 0.01f * o1;
            o2 = (o2 > 0.f) ? o2 : 0.01f * o2;
            o3 = (o3 > 0.f) ? o3 : 0.01f * o3;
        }
        out4.x += o0; out4.y += o1; out4.z += o2; out4.w += o3;
    }

    out4.x = to_tf32(out4.x); out4.y = to_tf32(out4.y);
    out4.z = to_tf32(out4.z); out4.w = to_tf32(out4.w);
    size_t off = (size_t)n * FF + h * DD + lane * 4;
    *reinterpret_cast<float4*>(hout + off) = out4;
}

// ---------------------------------------------------------------------------
// Launch: two-stream fork/join (graph-capturable); side stream runs the
// weight converts + CSR build concurrently with cvt + layer-0 GEMM.
// ---------------------------------------------------------------------------
extern "C" void kernel_launch(void* const* d_in, const int* in_sizes, int n_in,
                              void* d_out, int out_size)
{
    const float* x = (const float*)d_in[0];
    const int* src[2] = {(const int*)d_in[1], (const int*)d_in[3]};
    const int* dst[2] = {(const int*)d_in[2], (const int*)d_in[4]};
    const float* W [3] = {(const float*)d_in[5],  (const float*)d_in[9],  (const float*)d_in[13]};
    const float* al[3] = {(const float*)d_in[6],  (const float*)d_in[10], (const float*)d_in[14]};
    const float* ar[3] = {(const float*)d_in[7],  (const float*)d_in[11], (const float*)d_in[15]};
    const float* bb[3] = {(const float*)d_in[8],  (const float*)d_in[12], (const float*)d_in[16]};
    const float* Wout = (const float*)d_in[17];
    const float* bout = (const float*)d_in[18];
    float* out = (float*)d_out;

    float *feat, *h1, *h2, *xc, *w0c, *w1c, *w2c, *woc, *el2, *er2;
    int *deg, *cur, *rp, *csrc;
    cudaGetSymbolAddress((void**)&feat, g_feat);
    cudaGetSymbolAddress((void**)&h1,   g_h1);
    cudaGetSymbolAddress((void**)&h2,   g_h2);
    cudaGetSymbolAddress((void**)&xc,   g_xc);
    cudaGetSymbolAddress((void**)&w0c,  g_w0);
    cudaGetSymbolAddress((void**)&w1c,  g_w1);
    cudaGetSymbolAddress((void**)&w2c,  g_w2);
    cudaGetSymbolAddress((void**)&woc,  g_wo);
    cudaGetSymbolAddress((void**)&el2,  g_el);
    cudaGetSymbolAddress((void**)&er2,  g_er);
    cudaGetSymbolAddress((void**)&deg,  g_deg);
    cudaGetSymbolAddress((void**)&cur,  g_cur);
    cudaGetSymbolAddress((void**)&rp,   g_rp);
    cudaGetSymbolAddress((void**)&csrc, g_csrc);

    static cudaStream_t s2 = nullptr;
    static cudaEvent_t evRoot = nullptr, evW0 = nullptr, evSide = nullptr;
    static bool init_done = false;
    if (!init_done) {
        cudaFuncSetAttribute(gemm_pipe<false>, cudaFuncAttributeMaxDynamicSharedMemorySize, SMEM_BYTES);
        cudaFuncSetAttribute(gemm_pipe<true>,  cudaFuncAttributeMaxDynamicSharedMemorySize, SMEM_BYTES);
        cudaStreamCreateWithFlags(&s2, cudaStreamNonBlocking);
        cudaEventCreateWithFlags(&evRoot, cudaEventDisableTiming);
        cudaEventCreateWithFlags(&evW0,   cudaEventDisableTiming);
        cudaEventCreateWithFlags(&evSide, cudaEventDisableTiming);
        init_done = true;
    }

    const int neBlocks = (NE + 255) / 256;
    const int lgBlocks = (NN * HH * 32 + 255) / 256;
    const int agBlocks = (NN * HH + 7) / 8;
    const int gy = (NN + BM - 1) / BM;   // 313

    const float* Wc[3] = {w0c, w1c, w2c};
    const int Ks[3] = {1024, 512, 512};
    float* houts[3] = {h1, h2, h1};

    // ---- fork: side stream joins the capture via event on stream 0 ----
    cudaEventRecord(evRoot, 0);
    cudaStreamWaitEvent(s2, evRoot, 0);

    // side stream: weight preprocessing + CSR build
    wcat_kernel<<<(1024 * FF2 + 255) / 256, 256, 0, s2>>>(W[0], w0c, 1024);
    cudaEventRecord(evW0, s2);
    wcat_kernel<<<(512 * FF2 + 255) / 256, 256, 0, s2>>>(W[1], w1c, 512);
    wcat_kernel<<<(512 * FF2 + 255) / 256, 256, 0, s2>>>(W[2], w2c, 512);
    pad_wout_kernel<<<(FF * NOUTP + 255) / 256, 256, 0, s2>>>(Wout, woc);
    for (int t = 0; t < 2; t++) {
        int* rpt = rp + t * (NN + 1);
        int* cst = csrc + t * NE;
        cudaMemsetAsync(deg, 0, NN * sizeof(int), s2);
        hist_kernel<<<neBlocks, 256, 0, s2>>>(dst[t], deg);
        scan_kernel<<<1, 1024, 0, s2>>>(deg, rpt, cur);
        scatter_kernel<<<neBlocks, 256, 0, s2>>>(src[t], dst[t], cur, cst);
    }
    cudaEventRecord(evSide, s2);

    // main stream: input rounding, then layer-0 GEMM (needs w0c)
    {
        int n4 = NN * 1024 / 4;
        cvt_kernel<<<(n4 + 255) / 256, 256>>>(x, xc, n4);
    }
    cudaStreamWaitEvent(0, evW0, 0);
    {
        dim3 grid(FF2 / BN, gy);
        gemm_pipe<false><<<grid, 256, SMEM_BYTES>>>(xc, Wc[0], feat, NN, FF2, FF2, Ks[0], nullptr);
    }
    // join: everything after needs CSR / remaining weights
    cudaStreamWaitEvent(0, evSide, 0);

    const float* hin = xc;
    for (int L = 0; L < 3; L++) {
        float* hout = houts[L];
        if (L > 0) {
            dim3 grid(FF2 / BN, gy);
            gemm_pipe<false><<<grid, 256, SMEM_BYTES>>>(hin, Wc[L], feat, NN, FF2, FF2, Ks[L], nullptr);
        }
        logits2_kernel<<<lgBlocks, 256>>>(feat, al[L], ar[L], el2, er2);
        aggr2_kernel<<<agBlocks, 256>>>(rp, csrc, rp + (NN + 1), csrc + NE,
                                        el2, er2, feat, bb[L], hout,
                                        (L < 2) ? 1 : 0);
        hin = hout;
    }

    dim3 gridF((NOUT + BN - 1) / BN, gy);
    gemm_pipe<true><<<gridF, 256, SMEM_BYTES>>>(hin, woc, out, NN, NOUT, NOUTP, FF, bout);
}

// round 15
// speedup vs baseline: 1.5171x; 1.5171x over previous
#include <cuda_runtime.h>
#include <math.h>
#include <stdint.h>

// Problem constants (fixed-shape problem)
#define NN 40000      // nodes
#define NE 150000     // edges per type
#define HH 4          // heads
#define DD 128        // per-head dim
#define FF 512        // HH*DD
#define FF2 1024      // both edge types concatenated
#define NOUT 2983
#define NOUTP 2984    // padded (16B-aligned rows for cp.async)

// ---------------------------------------------------------------------------
// Scratch (device globals; no allocation allowed)
// ---------------------------------------------------------------------------
__device__ float g_feat[(size_t)NN * FF2];           // both types per layer
__device__ float g_h1  [(size_t)NN * FF];
__device__ float g_h2  [(size_t)NN * FF];
__device__ float g_xc  [(size_t)NN * 1024];          // tf32-rounded x
__device__ float g_w0  [1024 * FF2];                 // concat [K,1024] tf32
__device__ float g_w1  [512 * FF2];
__device__ float g_w2  [512 * FF2];
__device__ float g_wo  [FF * NOUTP];                 // tf32, padded Wout
__device__ float g_el  [2][NN * HH];                 // per edge type
__device__ float g_er  [2][NN * HH];
__device__ int   g_deg [NN];
__device__ int   g_cur [NN];
__device__ int   g_rp  [2][NN + 1];
__device__ int   g_csrc[2][NE];

// ---------------------------------------------------------------------------
// Helpers
// ---------------------------------------------------------------------------
__device__ __forceinline__ float to_tf32(float x)
{
    unsigned r;
    asm("cvt.rna.tf32.f32 %0, %1;" : "=r"(r) : "f"(x));
    return __uint_as_float(r);
}

__device__ __forceinline__ void mma_tf32(float c[4],
                                         float a0, float a1, float a2, float a3,
                                         float b0, float b1)
{
    asm volatile(
        "mma.sync.aligned.m16n8k8.row.col.f32.tf32.tf32.f32 "
        "{%0,%1,%2,%3}, {%4,%5,%6,%7}, {%8,%9}, {%0,%1,%2,%3};\n"
        : "+f"(c[0]), "+f"(c[1]), "+f"(c[2]), "+f"(c[3])
        : "r"(__float_as_uint(a0)), "r"(__float_as_uint(a1)),
          "r"(__float_as_uint(a2)), "r"(__float_as_uint(a3)),
          "r"(__float_as_uint(b0)), "r"(__float_as_uint(b1)));
}

__device__ __forceinline__ void cp_async16(uint32_t saddr, const void* gptr, int bytes)
{
    asm volatile("cp.async.cg.shared.global [%0], [%1], 16, %2;\n"
                 :: "r"(saddr), "l"(gptr), "r"(bytes));
}
__device__ __forceinline__ void cp_commit()
{
    asm volatile("cp.async.commit_group;\n");
}
__device__ __forceinline__ void cp_wait1()
{
    asm volatile("cp.async.wait_group 1;\n" ::: "memory");
}

// ---------------------------------------------------------------------------
// TF32 tensor-core GEMM, cp.async 3-stage pipeline, 2 CTAs/SM.
// CTA tile 128x128, BK=32, 256 threads (8 warps), warp tile 64x32.
// C[M,Ncols] = A[M,K] @ B[K,NB] (row-major), Ncols <= NB.
// (identical to the measured 2480us configuration)
// ---------------------------------------------------------------------------
#define BM 128
#define BN 128
#define BKK 32
#define STAGES 3
#define AS_LD 36
#define BS_LD 136
#define A_FLOATS (BM * AS_LD)                 // 4608
#define B_FLOATS (BKK * BS_LD)                // 4352
#define STG_FLOATS (A_FLOATS + B_FLOATS)      // 8960
#define SMEM_BYTES (STAGES * STG_FLOATS * 4)  // 107520 -> 2 CTAs/SM

extern __shared__ float smem_dyn[];

template <bool ADD_BIAS>
__global__ __launch_bounds__(256, 2)
void gemm_pipe(const float* __restrict__ A, const float* __restrict__ B,
               float* __restrict__ C, int M, int Ncols, int NB, int K,
               const float* __restrict__ bias)
{
    const int tid  = threadIdx.x;
    const int wid  = tid >> 5;
    const int lane = tid & 31;
    const int wm   = wid & 1;          // 2 row groups x 64
    const int wn   = wid >> 1;         // 4 col groups x 32
    const int g    = lane >> 2;
    const int q    = lane & 3;

    const int bm = blockIdx.y * BM;
    const int bn = blockIdx.x * BN;

    const uint32_t sbase = (uint32_t)__cvta_generic_to_shared(smem_dyn);

    float c[4][4][4];
    #pragma unroll
    for (int i = 0; i < 4; i++)
        #pragma unroll
        for (int j = 0; j < 4; j++)
            #pragma unroll
            for (int r = 0; r < 4; r++) c[i][j][r] = 0.f;

    const int nt = K / BKK;

    auto load_stage = [&](int s, int t) {
        const int k0 = t * BKK;
        const uint32_t ss = sbase + (uint32_t)(s * STG_FLOATS) * 4u;
        #pragma unroll
        for (int i = 0; i < 4; i++) {
            int f   = i * 256 + tid;
            int row = f >> 3;                 // 0..127
            int kc  = (f & 7) * 4;            // 0..28
            int m   = bm + row;
            const float* ga = (m < M) ? (A + (size_t)m * K + k0 + kc) : A;
            cp_async16(ss + (uint32_t)(row * AS_LD + kc) * 4u, ga, (m < M) ? 16 : 0);
        }
        #pragma unroll
        for (int i = 0; i < 4; i++) {
            int f    = i * 256 + tid;
            int brow = f >> 5;                // 0..31
            int bcol = (f & 31) * 4;          // 0..124
            int n    = bn + bcol;
            int rem  = NB - n;
            int bytes = rem >= 4 ? 16 : (rem > 0 ? rem * 4 : 0);
            const float* gb = (bytes > 0) ? (B + (size_t)(k0 + brow) * NB + n) : B;
            cp_async16(ss + (uint32_t)(A_FLOATS + brow * BS_LD + bcol) * 4u, gb, bytes);
        }
        cp_commit();
    };

    #pragma unroll
    for (int s = 0; s < STAGES - 1; s++)
        load_stage(s, s);

    for (int t = 0; t < nt; t++) {
        cp_wait1();
        __syncthreads();

        const float* As = smem_dyn + (t % STAGES) * STG_FLOATS;
        const float* Bs = As + A_FLOATS;

        #pragma unroll
        for (int ks = 0; ks < 4; ks++) {
            const int kb = ks * 8;
            float a[4][4], b[4][2];
            #pragma unroll
            for (int mi = 0; mi < 4; mi++) {
                int r = wm * 64 + mi * 16 + g;
                a[mi][0] = As[(r    ) * AS_LD + kb + q];
                a[mi][1] = As[(r + 8) * AS_LD + kb + q];
                a[mi][2] = As[(r    ) * AS_LD + kb + q + 4];
                a[mi][3] = As[(r + 8) * AS_LD + kb + q + 4];
            }
            #pragma unroll
            for (int nj = 0; nj < 4; nj++) {
                int cn = wn * 32 + nj * 8 + g;
                b[nj][0] = Bs[(kb + q    ) * BS_LD + cn];
                b[nj][1] = Bs[(kb + q + 4) * BS_LD + cn];
            }
            #pragma unroll
            for (int mi = 0; mi < 4; mi++)
                #pragma unroll
                for (int nj = 0; nj < 4; nj++)
                    mma_tf32(c[mi][nj], a[mi][0], a[mi][1], a[mi][2], a[mi][3],
                             b[nj][0], b[nj][1]);
        }

        if (t + STAGES - 1 < nt)
            load_stage((t + STAGES - 1) % STAGES, t + STAGES - 1);
        else
            cp_commit();
    }

    #pragma unroll
    for (int mi = 0; mi < 4; mi++) {
        int row0 = bm + wm * 64 + mi * 16 + g;
        #pragma unroll
        for (int nj = 0; nj < 4; nj++) {
            int col0 = bn + wn * 32 + nj * 8 + 2 * q;
            #pragma unroll
            for (int r = 0; r < 4; r++) {
                int row = row0 + (r >= 2 ? 8 : 0);
                int col = col0 + (r & 1);
                if (row < M && col < Ncols) {
                    float v = c[mi][nj][r];
                    if (ADD_BIAS) v += bias[col];
                    C[(size_t)row * Ncols + col] = v;
                }
            }
        }
    }
}

// ---------------------------------------------------------------------------
// Single fused prep kernel: tf32-round x; transpose/concat/round W0..W2;
// pad+round Wout. All segments are independent elementwise work.
// Segment sizes (in elements):
//   S0: x       NN*1024           (float4-vectorized: NN*256 iterations)
//   S1: W0      1024*FF2
//   S2: W1      512*FF2
//   S3: W2      512*FF2
//   S4: Wout    FF*NOUTP
// ---------------------------------------------------------------------------
#define P0 (NN * 256)                 // float4s of x
#define P1 (1024 * FF2)
#define P2 (512 * FF2)
#define P3 (512 * FF2)
#define P4 (FF * NOUTP)
#define PTOT (P0 + P1 + P2 + P3 + P4)

__global__ void prep_all_kernel(const float* __restrict__ x, float* __restrict__ xc,
                                const float* __restrict__ W0, float* __restrict__ w0c,
                                const float* __restrict__ W1, float* __restrict__ w1c,
                                const float* __restrict__ W2, float* __restrict__ w2c,
                                const float* __restrict__ Wo, float* __restrict__ woc)
{
    int i = blockIdx.x * blockDim.x + threadIdx.x;
    if (i >= PTOT) return;

    if (i < P0) {
        float4 v = reinterpret_cast<const float4*>(x)[i];
        v.x = to_tf32(v.x); v.y = to_tf32(v.y);
        v.z = to_tf32(v.z); v.w = to_tf32(v.w);
        reinterpret_cast<float4*>(xc)[i] = v;
        return;
    }
    i -= P0;
    if (i < P1) {
        int k = i >> 10, c = i & 1023, t = c >> 9, n = c & 511;
        w0c[i] = to_tf32(W0[((size_t)t * 1024 + k) * 512 + n]);
        return;
    }
    i -= P1;
    if (i < P2) {
        int k = i >> 10, c = i & 1023, t = c >> 9, n = c & 511;
        w1c[i] = to_tf32(W1[((size_t)t * 512 + k) * 512 + n]);
        return;
    }
    i -= P2;
    if (i < P3) {
        int k = i >> 10, c = i & 1023, t = c >> 9, n = c & 511;
        w2c[i] = to_tf32(W2[((size_t)t * 512 + k) * 512 + n]);
        return;
    }
    i -= P3;
    {
        int r = i / NOUTP, c = i - r * NOUTP;
        woc[i] = (c < NOUT) ? to_tf32(Wo[r * NOUT + c]) : 0.f;
    }
}

// ---------------------------------------------------------------------------
// CSR construction
// ---------------------------------------------------------------------------
__global__ void hist_kernel(const int* __restrict__ dst, int* __restrict__ deg)
{
    int i = blockIdx.x * blockDim.x + threadIdx.x;
    if (i < NE) atomicAdd(&deg[dst[i]], 1);
}

__global__ __launch_bounds__(1024)
void scan_kernel(const int* __restrict__ deg, int* __restrict__ rp,
                 int* __restrict__ cur)
{
    const int CH = 40;
    __shared__ int sm[1024];
    int tid = threadIdx.x;
    int start = tid * CH;

    int sum = 0;
    #pragma unroll 4
    for (int j = 0; j < CH; j++) {
        int i = start + j;
        if (i < NN) sum += deg[i];
    }
    sm[tid] = sum;
    __syncthreads();
    for (int off = 1; off < 1024; off <<= 1) {
        int t = (tid >= off) ? sm[tid - off] : 0;
        __syncthreads();
        sm[tid] += t;
        __syncthreads();
    }
    int run = sm[tid] - sum;
    for (int j = 0; j < CH; j++) {
        int i = start + j;
        if (i < NN) {
            rp[i]  = run;
            cur[i] = run;
            run += deg[i];
        }
    }
    if (tid == 1023) rp[NN] = sm[1023];
}

__global__ void scatter_kernel(const int* __restrict__ src, const int* __restrict__ dst,
                               int* __restrict__ cur, int* __restrict__ csrc)
{
    int i = blockIdx.x * blockDim.x + threadIdx.x;
    if (i < NE) {
        int p = atomicAdd(&cur[dst[i]], 1);
        csrc[p] = src[i];
    }
}

// ---------------------------------------------------------------------------
// Attention logits, BOTH edge types in one pass. One warp per (node, head).
// ---------------------------------------------------------------------------
__global__ void logits2_kernel(const float* __restrict__ feat,
                               const float* __restrict__ al,
                               const float* __restrict__ ar,
                               float* __restrict__ el, float* __restrict__ er)
{
    int gw   = (blockIdx.x * blockDim.x + threadIdx.x) >> 5;
    int lane = threadIdx.x & 31;
    if (gw >= NN * HH) return;
    int n = gw >> 2;
    int h = gw & 3;

    #pragma unroll
    for (int t = 0; t < 2; t++) {
        float4 fv = reinterpret_cast<const float4*>(feat + (size_t)n * FF2 + t * FF + h * DD)[lane];
        float4 av = reinterpret_cast<const float4*>(al + t * FF + h * DD)[lane];
        float4 rv = reinterpret_cast<const float4*>(ar + t * FF + h * DD)[lane];

        float dl = fv.x * av.x + fv.y * av.y + fv.z * av.z + fv.w * av.w;
        float dr = fv.x * rv.x + fv.y * rv.y + fv.z * rv.z + fv.w * rv.w;
        #pragma unroll
        for (int o = 16; o; o >>= 1) {
            dl += __shfl_xor_sync(0xFFFFFFFFu, dl, o);
            dr += __shfl_xor_sync(0xFFFFFFFFu, dr, o);
        }
        if (lane == 0) {
            el[t * (NN * HH) + gw] = dl;
            er[t * (NN * HH) + gw] = dr;
        }
    }
}

// ---------------------------------------------------------------------------
// Fused aggregation, BOTH edge types: per (dst,head) warp,
//   out = act(softmax-agg_t0 + b0) + act(softmax-agg_t1 + b1), tf32-rounded.
// ---------------------------------------------------------------------------
__global__ __launch_bounds__(256)
void aggr2_kernel(const int* __restrict__ rp0, const int* __restrict__ cs0,
                  const int* __restrict__ rp1, const int* __restrict__ cs1,
                  const float* __restrict__ el, const float* __restrict__ er,
                  const float* __restrict__ feat, const float* __restrict__ bias,
                  float* __restrict__ hout, int activate)
{
    int gw   = (blockIdx.x * blockDim.x + threadIdx.x) >> 5;
    int lane = threadIdx.x & 31;
    if (gw >= NN * HH) return;
    int n = gw >> 2;
    int h = gw & 3;

    float4 out4 = make_float4(0.f, 0.f, 0.f, 0.f);

    #pragma unroll
    for (int t = 0; t < 2; t++) {
        const int* rp = t ? rp1 : rp0;
        const int* cs = t ? cs1 : cs0;
        const float* elt = el + t * (NN * HH);
        float erd = er[t * (NN * HH) + gw];
        const float* ft = feat + t * FF;

        int beg = rp[n];
        int end = rp[n + 1];

        float mx = -INFINITY;
        for (int i = beg + lane; i < end; i += 32) {
            int s = cs[i];
            float v = elt[s * HH + h] + erd;
            v = (v > 0.f) ? v : 0.2f * v;
            mx = fmaxf(mx, v);
        }
        #pragma unroll
        for (int o = 16; o; o >>= 1)
            mx = fmaxf(mx, __shfl_xor_sync(0xFFFFFFFFu, mx, o));

        float ss = 0.f;
        for (int i = beg + lane; i < end; i += 32) {
            int s = cs[i];
            float v = elt[s * HH + h] + erd;
            v = (v > 0.f) ? v : 0.2f * v;
            ss += __expf(v - mx);
        }
        #pragma unroll
        for (int o = 16; o; o >>= 1)
            ss += __shfl_xor_sync(0xFFFFFFFFu, ss, o);
        float inv = (end > beg) ? 1.f / ss : 0.f;

        float4 acc = make_float4(0.f, 0.f, 0.f, 0.f);
        for (int i = beg; i < end; i++) {
            int s = cs[i];
            float v = elt[s * HH + h] + erd;
            v = (v > 0.f) ? v : 0.2f * v;
            float a = __expf(v - mx) * inv;
            float4 fv = reinterpret_cast<const float4*>(ft + (size_t)s * FF2 + h * DD)[lane];
            acc.x = fmaf(a, fv.x, acc.x);
            acc.y = fmaf(a, fv.y, acc.y);
            acc.z = fmaf(a, fv.z, acc.z);
            acc.w = fmaf(a, fv.w, acc.w);
        }

        float4 b4 = reinterpret_cast<const float4*>(bias + t * FF + h * DD)[lane];
        float o0 = acc.x + b4.x, o1 = acc.y + b4.y;
        float o2 = acc.z + b4.z, o3 = acc.w + b4.w;
        if (activate) {
            o0 = (o0 > 0.f) ? o0 : 0.01f * o0;
            o1 = (o1 > 0.f) ? o1 : 0.01f * o1;
            o2 = (o2 > 0.f) ? o2 : 0.01f * o2;
            o3 = (o3 > 0.f) ? o3 : 0.01f * o3;
        }
        out4.x += o0; out4.y += o1; out4.z += o2; out4.w += o3;
    }

    out4.x = to_tf32(out4.x); out4.y = to_tf32(out4.y);
    out4.z = to_tf32(out4.z); out4.w = to_tf32(out4.w);
    size_t off = (size_t)n * FF + h * DD + lane * 4;
    *reinterpret_cast<float4*>(hout + off) = out4;
}

// ---------------------------------------------------------------------------
// Launch (single stream; R13 ordering restored)
// ---------------------------------------------------------------------------
extern "C" void kernel_launch(void* const* d_in, const int* in_sizes, int n_in,
                              void* d_out, int out_size)
{
    const float* x = (const float*)d_in[0];
    const int* src[2] = {(const int*)d_in[1], (const int*)d_in[3]};
    const int* dst[2] = {(const int*)d_in[2], (const int*)d_in[4]};
    const float* W [3] = {(const float*)d_in[5],  (const float*)d_in[9],  (const float*)d_in[13]};
    const float* al[3] = {(const float*)d_in[6],  (const float*)d_in[10], (const float*)d_in[14]};
    const float* ar[3] = {(const float*)d_in[7],  (const float*)d_in[11], (const float*)d_in[15]};
    const float* bb[3] = {(const float*)d_in[8],  (const float*)d_in[12], (const float*)d_in[16]};
    const float* Wout = (const float*)d_in[17];
    const float* bout = (const float*)d_in[18];
    float* out = (float*)d_out;

    float *feat, *h1, *h2, *xc, *w0c, *w1c, *w2c, *woc, *el2, *er2;
    int *deg, *cur, *rp, *csrc;
    cudaGetSymbolAddress((void**)&feat, g_feat);
    cudaGetSymbolAddress((void**)&h1,   g_h1);
    cudaGetSymbolAddress((void**)&h2,   g_h2);
    cudaGetSymbolAddress((void**)&xc,   g_xc);
    cudaGetSymbolAddress((void**)&w0c,  g_w0);
    cudaGetSymbolAddress((void**)&w1c,  g_w1);
    cudaGetSymbolAddress((void**)&w2c,  g_w2);
    cudaGetSymbolAddress((void**)&woc,  g_wo);
    cudaGetSymbolAddress((void**)&el2,  g_el);
    cudaGetSymbolAddress((void**)&er2,  g_er);
    cudaGetSymbolAddress((void**)&deg,  g_deg);
    cudaGetSymbolAddress((void**)&cur,  g_cur);
    cudaGetSymbolAddress((void**)&rp,   g_rp);
    cudaGetSymbolAddress((void**)&csrc, g_csrc);

    static bool init_done = false;
    if (!init_done) {
        cudaFuncSetAttribute(gemm_pipe<false>, cudaFuncAttributeMaxDynamicSharedMemorySize, SMEM_BYTES);
        cudaFuncSetAttribute(gemm_pipe<true>,  cudaFuncAttributeMaxDynamicSharedMemorySize, SMEM_BYTES);
        init_done = true;
    }

    const int neBlocks = (NE + 255) / 256;
    const int lgBlocks = (NN * HH * 32 + 255) / 256;
    const int agBlocks = (NN * HH + 7) / 8;
    const int gy = (NN + BM - 1) / BM;   // 313

    const float* Wc[3] = {w0c, w1c, w2c};
    const int Ks[3] = {1024, 512, 512};
    float* houts[3] = {h1, h2, h1};

    // ---- single fused prep launch (x round + weight concat/pad) ----
    prep_all_kernel<<<(PTOT + 255) / 256, 256>>>(x, xc, W[0], w0c, W[1], w1c,
                                                 W[2], w2c, Wout, woc);

    // ---- Layer 0 GEMM ----
    {
        dim3 grid(FF2 / BN, gy);
        gemm_pipe<false><<<grid, 256, SMEM_BYTES>>>(xc, Wc[0], feat, NN, FF2, FF2, Ks[0], nullptr);
    }

    // ---- CSR for both edge types (independent of GEMM output) ----
    for (int t = 0; t < 2; t++) {
        int* rpt = rp + t * (NN + 1);
        int* cst = csrc + t * NE;
        cudaMemsetAsync(deg, 0, NN * sizeof(int), 0);
        hist_kernel<<<neBlocks, 256>>>(dst[t], deg);
        scan_kernel<<<1, 1024>>>(deg, rpt, cur);
        scatter_kernel<<<neBlocks, 256>>>(src[t], dst[t], cur, cst);
    }

    const float* hin = xc;
    for (int L = 0; L < 3; L++) {
        float* hout = houts[L];
        if (L > 0) {
            dim3 grid(FF2 / BN, gy);
            gemm_pipe<false><<<grid, 256, SMEM_BYTES>>>(hin, Wc[L], feat, NN, FF2, FF2, Ks[L], nullptr);
        }
        logits2_kernel<<<lgBlocks, 256>>>(feat, al[L], ar[L], el2, er2);
        aggr2_kernel<<<agBlocks, 256>>>(rp, csrc, rp + (NN + 1), csrc + NE,
                                        el2, er2, feat, bb[L], hout,
                                        (L < 2) ? 1 : 0);
        hin = hout;
    }

    dim3 gridF((NOUT + BN - 1) / BN, gy);
    gemm_pipe<true><<<gridF, 256, SMEM_BYTES>>>(hin, woc, out, NN, NOUT, NOUTP, FF, bout);
}

// round 16
// speedup vs baseline: 1.5823x; 1.0430x over previous
#include <cuda_runtime.h>
#include <math.h>
#include <stdint.h>

// Problem constants (fixed-shape problem)
#define NN 40000      // nodes
#define NE 150000     // edges per type
#define HH 4          // heads
#define DD 128        // per-head dim
#define FF 512        // HH*DD
#define FF2 1024      // both edge types concatenated
#define NOUT 2983
#define NOUTP 2984    // padded (16B-aligned rows for cp.async)
#define SCB 157       // scan blocks: ceil(NN/256)

// ---------------------------------------------------------------------------
// Scratch (device globals; no allocation allowed)
// ---------------------------------------------------------------------------
__device__ float g_feat[(size_t)NN * FF2];           // both types per layer
__device__ float g_h1  [(size_t)NN * FF];
__device__ float g_h2  [(size_t)NN * FF];
__device__ float g_xc  [(size_t)NN * 1024];          // tf32-rounded x
__device__ float g_w0  [1024 * FF2];                 // concat [K,1024] tf32
__device__ float g_w1  [512 * FF2];
__device__ float g_w2  [512 * FF2];
__device__ float g_wo  [FF * NOUTP];                 // tf32, padded Wout
__device__ float g_el  [2][NN * HH];                 // per edge type
__device__ float g_er  [2][NN * HH];
__device__ int   g_deg [NN];
__device__ int   g_cur [NN];
__device__ int   g_bsum[256];
__device__ int   g_rp  [2][NN + 1];
__device__ int   g_csrc[2][NE];

// ---------------------------------------------------------------------------
// Helpers
// ---------------------------------------------------------------------------
__device__ __forceinline__ float to_tf32(float x)
{
    unsigned r;
    asm("cvt.rna.tf32.f32 %0, %1;" : "=r"(r) : "f"(x));
    return __uint_as_float(r);
}

__device__ __forceinline__ void mma_tf32(float c[4],
                                         float a0, float a1, float a2, float a3,
                                         float b0, float b1)
{
    asm volatile(
        "mma.sync.aligned.m16n8k8.row.col.f32.tf32.tf32.f32 "
        "{%0,%1,%2,%3}, {%4,%5,%6,%7}, {%8,%9}, {%0,%1,%2,%3};\n"
        : "+f"(c[0]), "+f"(c[1]), "+f"(c[2]), "+f"(c[3])
        : "r"(__float_as_uint(a0)), "r"(__float_as_uint(a1)),
          "r"(__float_as_uint(a2)), "r"(__float_as_uint(a3)),
          "r"(__float_as_uint(b0)), "r"(__float_as_uint(b1)));
}

__device__ __forceinline__ void cp_async16(uint32_t saddr, const void* gptr, int bytes)
{
    asm volatile("cp.async.cg.shared.global [%0], [%1], 16, %2;\n"
                 :: "r"(saddr), "l"(gptr), "r"(bytes));
}
__device__ __forceinline__ void cp_commit()
{
    asm volatile("cp.async.commit_group;\n");
}
__device__ __forceinline__ void cp_wait1()
{
    asm volatile("cp.async.wait_group 1;\n" ::: "memory");
}

// ---------------------------------------------------------------------------
// TF32 tensor-core GEMM, cp.async 3-stage pipeline, 2 CTAs/SM.
// CTA tile 128x128, BK=32, 256 threads (8 warps), warp tile 64x32.
// (identical to the measured 2461us configuration)
// ---------------------------------------------------------------------------
#define BM 128
#define BN 128
#define BKK 32
#define STAGES 3
#define AS_LD 36
#define BS_LD 136
#define A_FLOATS (BM * AS_LD)                 // 4608
#define B_FLOATS (BKK * BS_LD)                // 4352
#define STG_FLOATS (A_FLOATS + B_FLOATS)      // 8960
#define SMEM_BYTES (STAGES * STG_FLOATS * 4)  // 107520 -> 2 CTAs/SM

extern __shared__ float smem_dyn[];

template <bool ADD_BIAS>
__global__ __launch_bounds__(256, 2)
void gemm_pipe(const float* __restrict__ A, const float* __restrict__ B,
               float* __restrict__ C, int M, int Ncols, int NB, int K,
               const float* __restrict__ bias)
{
    const int tid  = threadIdx.x;
    const int wid  = tid >> 5;
    const int lane = tid & 31;
    const int wm   = wid & 1;          // 2 row groups x 64
    const int wn   = wid >> 1;         // 4 col groups x 32
    const int g    = lane >> 2;
    const int q    = lane & 3;

    const int bm = blockIdx.y * BM;
    const int bn = blockIdx.x * BN;

    const uint32_t sbase = (uint32_t)__cvta_generic_to_shared(smem_dyn);

    float c[4][4][4];
    #pragma unroll
    for (int i = 0; i < 4; i++)
        #pragma unroll
        for (int j = 0; j < 4; j++)
            #pragma unroll
            for (int r = 0; r < 4; r++) c[i][j][r] = 0.f;

    const int nt = K / BKK;

    auto load_stage = [&](int s, int t) {
        const int k0 = t * BKK;
        const uint32_t ss = sbase + (uint32_t)(s * STG_FLOATS) * 4u;
        #pragma unroll
        for (int i = 0; i < 4; i++) {
            int f   = i * 256 + tid;
            int row = f >> 3;                 // 0..127
            int kc  = (f & 7) * 4;            // 0..28
            int m   = bm + row;
            const float* ga = (m < M) ? (A + (size_t)m * K + k0 + kc) : A;
            cp_async16(ss + (uint32_t)(row * AS_LD + kc) * 4u, ga, (m < M) ? 16 : 0);
        }
        #pragma unroll
        for (int i = 0; i < 4; i++) {
            int f    = i * 256 + tid;
            int brow = f >> 5;                // 0..31
            int bcol = (f & 31) * 4;          // 0..124
            int n    = bn + bcol;
            int rem  = NB - n;
            int bytes = rem >= 4 ? 16 : (rem > 0 ? rem * 4 : 0);
            const float* gb = (bytes > 0) ? (B + (size_t)(k0 + brow) * NB + n) : B;
            cp_async16(ss + (uint32_t)(A_FLOATS + brow * BS_LD + bcol) * 4u, gb, bytes);
        }
        cp_commit();
    };

    #pragma unroll
    for (int s = 0; s < STAGES - 1; s++)
        load_stage(s, s);

    for (int t = 0; t < nt; t++) {
        cp_wait1();
        __syncthreads();

        const float* As = smem_dyn + (t % STAGES) * STG_FLOATS;
        const float* Bs = As + A_FLOATS;

        #pragma unroll
        for (int ks = 0; ks < 4; ks++) {
            const int kb = ks * 8;
            float a[4][4], b[4][2];
            #pragma unroll
            for (int mi = 0; mi < 4; mi++) {
                int r = wm * 64 + mi * 16 + g;
                a[mi][0] = As[(r    ) * AS_LD + kb + q];
                a[mi][1] = As[(r + 8) * AS_LD + kb + q];
                a[mi][2] = As[(r    ) * AS_LD + kb + q + 4];
                a[mi][3] = As[(r + 8) * AS_LD + kb + q + 4];
            }
            #pragma unroll
            for (int nj = 0; nj < 4; nj++) {
                int cn = wn * 32 + nj * 8 + g;
                b[nj][0] = Bs[(kb + q    ) * BS_LD + cn];
                b[nj][1] = Bs[(kb + q + 4) * BS_LD + cn];
            }
            #pragma unroll
            for (int mi = 0; mi < 4; mi++)
                #pragma unroll
                for (int nj = 0; nj < 4; nj++)
                    mma_tf32(c[mi][nj], a[mi][0], a[mi][1], a[mi][2], a[mi][3],
                             b[nj][0], b[nj][1]);
        }

        if (t + STAGES - 1 < nt)
            load_stage((t + STAGES - 1) % STAGES, t + STAGES - 1);
        else
            cp_commit();
    }

    #pragma unroll
    for (int mi = 0; mi < 4; mi++) {
        int row0 = bm + wm * 64 + mi * 16 + g;
        #pragma unroll
        for (int nj = 0; nj < 4; nj++) {
            int col0 = bn + wn * 32 + nj * 8 + 2 * q;
            #pragma unroll
            for (int r = 0; r < 4; r++) {
                int row = row0 + (r >= 2 ? 8 : 0);
                int col = col0 + (r & 1);
                if (row < M && col < Ncols) {
                    float v = c[mi][nj][r];
                    if (ADD_BIAS) v += bias[col];
                    C[(size_t)row * Ncols + col] = v;
                }
            }
        }
    }
}

// ---------------------------------------------------------------------------
// Single fused prep kernel (identical to R15)
// ---------------------------------------------------------------------------
#define P0 (NN * 256)                 // float4s of x
#define P1 (1024 * FF2)
#define P2 (512 * FF2)
#define P3 (512 * FF2)
#define P4 (FF * NOUTP)
#define PTOT (P0 + P1 + P2 + P3 + P4)

__global__ void prep_all_kernel(const float* __restrict__ x, float* __restrict__ xc,
                                const float* __restrict__ W0, float* __restrict__ w0c,
                                const float* __restrict__ W1, float* __restrict__ w1c,
                                const float* __restrict__ W2, float* __restrict__ w2c,
                                const float* __restrict__ Wo, float* __restrict__ woc)
{
    int i = blockIdx.x * blockDim.x + threadIdx.x;
    if (i >= PTOT) return;

    if (i < P0) {
        float4 v = reinterpret_cast<const float4*>(x)[i];
        v.x = to_tf32(v.x); v.y = to_tf32(v.y);
        v.z = to_tf32(v.z); v.w = to_tf32(v.w);
        reinterpret_cast<float4*>(xc)[i] = v;
        return;
    }
    i -= P0;
    if (i < P1) {
        int k = i >> 10, c = i & 1023, t = c >> 9, n = c & 511;
        w0c[i] = to_tf32(W0[((size_t)t * 1024 + k) * 512 + n]);
        return;
    }
    i -= P1;
    if (i < P2) {
        int k = i >> 10, c = i & 1023, t = c >> 9, n = c & 511;
        w1c[i] = to_tf32(W1[((size_t)t * 512 + k) * 512 + n]);
        return;
    }
    i -= P2;
    if (i < P3) {
        int k = i >> 10, c = i & 1023, t = c >> 9, n = c & 511;
        w2c[i] = to_tf32(W2[((size_t)t * 512 + k) * 512 + n]);
        return;
    }
    i -= P3;
    {
        int r = i / NOUTP, c = i - r * NOUTP;
        woc[i] = (c < NOUT) ? to_tf32(Wo[r * NOUT + c]) : 0.f;
    }
}

// ---------------------------------------------------------------------------
// CSR construction: histogram + two-level parallel scan + scatter
// ---------------------------------------------------------------------------
__global__ void hist_kernel(const int* __restrict__ dst, int* __restrict__ deg)
{
    int i = blockIdx.x * blockDim.x + threadIdx.x;
    if (i < NE) atomicAdd(&deg[dst[i]], 1);
}

// scan1: per-block exclusive scan of deg into rp; block total into bsum.
__global__ __launch_bounds__(256)
void scan1_kernel(const int* __restrict__ deg, int* __restrict__ rp,
                  int* __restrict__ bsum)
{
    __shared__ int sm[256];
    int tid = threadIdx.x;
    int i = blockIdx.x * 256 + tid;
    int v = (i < NN) ? deg[i] : 0;
    sm[tid] = v;
    __syncthreads();
    #pragma unroll
    for (int off = 1; off < 256; off <<= 1) {
        int t = (tid >= off) ? sm[tid - off] : 0;
        __syncthreads();
        sm[tid] += t;
        __syncthreads();
    }
    if (i < NN) rp[i] = sm[tid] - v;          // exclusive within block
    if (tid == 255) bsum[blockIdx.x] = sm[255];
}

// scan2: single block exclusive scan of SCB block totals (SCB <= 256).
__global__ __launch_bounds__(256)
void scan2_kernel(int* __restrict__ bsum)
{
    __shared__ int sm[256];
    int tid = threadIdx.x;
    int v = (tid < SCB) ? bsum[tid] : 0;
    sm[tid] = v;
    __syncthreads();
    #pragma unroll
    for (int off = 1; off < 256; off <<= 1) {
        int t = (tid >= off) ? sm[tid - off] : 0;
        __syncthreads();
        sm[tid] += t;
        __syncthreads();
    }
    if (tid < SCB) bsum[tid] = sm[tid] - v;   // exclusive block offsets
}

// scan3: add block offsets; produce final rp and cur; rp[NN] = NE.
__global__ __launch_bounds__(256)
void scan3_kernel(int* __restrict__ rp, int* __restrict__ cur,
                  const int* __restrict__ bsum)
{
    int i = blockIdx.x * 256 + threadIdx.x;
    if (i < NN) {
        int v = rp[i] + bsum[blockIdx.x];
        rp[i]  = v;
        cur[i] = v;
    }
    if (i == 0) rp[NN] = NE;
}

__global__ void scatter_kernel(const int* __restrict__ src, const int* __restrict__ dst,
                               int* __restrict__ cur, int* __restrict__ csrc)
{
    int i = blockIdx.x * blockDim.x + threadIdx.x;
    if (i < NE) {
        int p = atomicAdd(&cur[dst[i]], 1);
        csrc[p] = src[i];
    }
}

// ---------------------------------------------------------------------------
// Attention logits, BOTH edge types in one pass. One warp per (node, head).
// ---------------------------------------------------------------------------
__global__ void logits2_kernel(const float* __restrict__ feat,
                               const float* __restrict__ al,
                               const float* __restrict__ ar,
                               float* __restrict__ el, float* __restrict__ er)
{
    int gw   = (blockIdx.x * blockDim.x + threadIdx.x) >> 5;
    int lane = threadIdx.x & 31;
    if (gw >= NN * HH) return;
    int n = gw >> 2;
    int h = gw & 3;

    #pragma unroll
    for (int t = 0; t < 2; t++) {
        float4 fv = reinterpret_cast<const float4*>(feat + (size_t)n * FF2 + t * FF + h * DD)[lane];
        float4 av = reinterpret_cast<const float4*>(al + t * FF + h * DD)[lane];
        float4 rv = reinterpret_cast<const float4*>(ar + t * FF + h * DD)[lane];

        float dl = fv.x * av.x + fv.y * av.y + fv.z * av.z + fv.w * av.w;
        float dr = fv.x * rv.x + fv.y * rv.y + fv.z * rv.z + fv.w * rv.w;
        #pragma unroll
        for (int o = 16; o; o >>= 1) {
            dl += __shfl_xor_sync(0xFFFFFFFFu, dl, o);
            dr += __shfl_xor_sync(0xFFFFFFFFu, dr, o);
        }
        if (lane == 0) {
            el[t * (NN * HH) + gw] = dl;
            er[t * (NN * HH) + gw] = dr;
        }
    }
}

// ---------------------------------------------------------------------------
// Fused aggregation, BOTH edge types (identical to R15)
// ---------------------------------------------------------------------------
__global__ __launch_bounds__(256)
void aggr2_kernel(const int* __restrict__ rp0, const int* __restrict__ cs0,
                  const int* __restrict__ rp1, const int* __restrict__ cs1,
                  const float* __restrict__ el, const float* __restrict__ er,
                  const float* __restrict__ feat, const float* __restrict__ bias,
                  float* __restrict__ hout, int activate)
{
    int gw   = (blockIdx.x * blockDim.x + threadIdx.x) >> 5;
    int lane = threadIdx.x & 31;
    if (gw >= NN * HH) return;
    int n = gw >> 2;
    int h = gw & 3;

    float4 out4 = make_float4(0.f, 0.f, 0.f, 0.f);

    #pragma unroll
    for (int t = 0; t < 2; t++) {
        const int* rp = t ? rp1 : rp0;
        const int* cs = t ? cs1 : cs0;
        const float* elt = el + t * (NN * HH);
        float erd = er[t * (NN * HH) + gw];
        const float* ft = feat + t * FF;

        int beg = rp[n];
        int end = rp[n + 1];

        float mx = -INFINITY;
        for (int i = beg + lane; i < end; i += 32) {
            int s = cs[i];
            float v = elt[s * HH + h] + erd;
            v = (v > 0.f) ? v : 0.2f * v;
            mx = fmaxf(mx, v);
        }
        #pragma unroll
        for (int o = 16; o; o >>= 1)
            mx = fmaxf(mx, __shfl_xor_sync(0xFFFFFFFFu, mx, o));

        float ss = 0.f;
        for (int i = beg + lane; i < end; i += 32) {
            int s = cs[i];
            float v = elt[s * HH + h] + erd;
            v = (v > 0.f) ? v : 0.2f * v;
            ss += __expf(v - mx);
        }
        #pragma unroll
        for (int o = 16; o; o >>= 1)
            ss += __shfl_xor_sync(0xFFFFFFFFu, ss, o);
        float inv = (end > beg) ? 1.f / ss : 0.f;

        float4 acc = make_float4(0.f, 0.f, 0.f, 0.f);
        for (int i = beg; i < end; i++) {
            int s = cs[i];
            float v = elt[s * HH + h] + erd;
            v = (v > 0.f) ? v : 0.2f * v;
            float a = __expf(v - mx) * inv;
            float4 fv = reinterpret_cast<const float4*>(ft + (size_t)s * FF2 + h * DD)[lane];
            acc.x = fmaf(a, fv.x, acc.x);
            acc.y = fmaf(a, fv.y, acc.y);
            acc.z = fmaf(a, fv.z, acc.z);
            acc.w = fmaf(a, fv.w, acc.w);
        }

        float4 b4 = reinterpret_cast<const float4*>(bias + t * FF + h * DD)[lane];
        float o0 = acc.x + b4.x, o1 = acc.y + b4.y;
        float o2 = acc.z + b4.z, o3 = acc.w + b4.w;
        if (activate) {
            o0 = (o0 > 0.f) ? o0 : 0.01f * o0;
            o1 = (o1 > 0.f) ? o1 : 0.01f * o1;
            o2 = (o2 > 0.f) ? o2 : 0.01f * o2;
            o3 = (o3 > 0.f) ? o3 : 0.01f * o3;
        }
        out4.x += o0; out4.y += o1; out4.z += o2; out4.w += o3;
    }

    out4.x = to_tf32(out4.x); out4.y = to_tf32(out4.y);
    out4.z = to_tf32(out4.z); out4.w = to_tf32(out4.w);
    size_t off = (size_t)n * FF + h * DD + lane * 4;
    *reinterpret_cast<float4*>(hout + off) = out4;
}

// ---------------------------------------------------------------------------
// Launch (single stream)
// ---------------------------------------------------------------------------
extern "C" void kernel_launch(void* const* d_in, const int* in_sizes, int n_in,
                              void* d_out, int out_size)
{
    const float* x = (const float*)d_in[0];
    const int* src[2] = {(const int*)d_in[1], (const int*)d_in[3]};
    const int* dst[2] = {(const int*)d_in[2], (const int*)d_in[4]};
    const float* W [3] = {(const float*)d_in[5],  (const float*)d_in[9],  (const float*)d_in[13]};
    const float* al[3] = {(const float*)d_in[6],  (const float*)d_in[10], (const float*)d_in[14]};
    const float* ar[3] = {(const float*)d_in[7],  (const float*)d_in[11], (const float*)d_in[15]};
    const float* bb[3] = {(const float*)d_in[8],  (const float*)d_in[12], (const float*)d_in[16]};
    const float* Wout = (const float*)d_in[17];
    const float* bout = (const float*)d_in[18];
    float* out = (float*)d_out;

    float *feat, *h1, *h2, *xc, *w0c, *w1c, *w2c, *woc, *el2, *er2;
    int *deg, *cur, *bsum, *rp, *csrc;
    cudaGetSymbolAddress((void**)&feat, g_feat);
    cudaGetSymbolAddress((void**)&h1,   g_h1);
    cudaGetSymbolAddress((void**)&h2,   g_h2);
    cudaGetSymbolAddress((void**)&xc,   g_xc);
    cudaGetSymbolAddress((void**)&w0c,  g_w0);
    cudaGetSymbolAddress((void**)&w1c,  g_w1);
    cudaGetSymbolAddress((void**)&w2c,  g_w2);
    cudaGetSymbolAddress((void**)&woc,  g_wo);
    cudaGetSymbolAddress((void**)&el2,  g_el);
    cudaGetSymbolAddress((void**)&er2,  g_er);
    cudaGetSymbolAddress((void**)&deg,  g_deg);
    cudaGetSymbolAddress((void**)&cur,  g_cur);
    cudaGetSymbolAddress((void**)&bsum, g_bsum);
    cudaGetSymbolAddress((void**)&rp,   g_rp);
    cudaGetSymbolAddress((void**)&csrc, g_csrc);

    static bool init_done = false;
    if (!init_done) {
        cudaFuncSetAttribute(gemm_pipe<false>, cudaFuncAttributeMaxDynamicSharedMemorySize, SMEM_BYTES);
        cudaFuncSetAttribute(gemm_pipe<true>,  cudaFuncAttributeMaxDynamicSharedMemorySize, SMEM_BYTES);
        init_done = true;
    }

    const int neBlocks = (NE + 255) / 256;
    const int lgBlocks = (NN * HH * 32 + 255) / 256;
    const int agBlocks = (NN * HH + 7) / 8;
    const int gy = (NN + BM - 1) / BM;   // 313

    const float* Wc[3] = {w0c, w1c, w2c};
    const int Ks[3] = {1024, 512, 512};
    float* houts[3] = {h1, h2, h1};

    // ---- single fused prep launch (x round + weight concat/pad) ----
    prep_all_kernel<<<(PTOT + 255) / 256, 256>>>(x, xc, W[0], w0c, W[1], w1c,
                                                 W[2], w2c, Wout, woc);

    // ---- Layer 0 GEMM ----
    {
        dim3 grid(FF2 / BN, gy);
        gemm_pipe<false><<<grid, 256, SMEM_BYTES>>>(xc, Wc[0], feat, NN, FF2, FF2, Ks[0], nullptr);
    }

    // ---- CSR for both edge types (two-level parallel scan) ----
    for (int t = 0; t < 2; t++) {
        int* rpt = rp + t * (NN + 1);
        int* cst = csrc + t * NE;
        cudaMemsetAsync(deg, 0, NN * sizeof(int), 0);
        hist_kernel<<<neBlocks, 256>>>(dst[t], deg);
        scan1_kernel<<<SCB, 256>>>(deg, rpt, bsum);
        scan2_kernel<<<1, 256>>>(bsum);
        scan3_kernel<<<SCB, 256>>>(rpt, cur, bsum);
        scatter_kernel<<<neBlocks, 256>>>(src[t], dst[t], cur, cst);
    }

    const float* hin = xc;
    for (int L = 0; L < 3; L++) {
        float* hout = houts[L];
        if (L > 0) {
            dim3 grid(FF2 / BN, gy);
            gemm_pipe<false><<<grid, 256, SMEM_BYTES>>>(hin, Wc[L], feat, NN, FF2, FF2, Ks[L], nullptr);
        }
        logits2_kernel<<<lgBlocks, 256>>>(feat, al[L], ar[L], el2, er2);
        aggr2_kernel<<<agBlocks, 256>>>(rp, csrc, rp + (NN + 1), csrc + NE,
                                        el2, er2, feat, bb[L], hout,
                                        (L < 2) ? 1 : 0);
        hin = hout;
    }

    dim3 gridF((NOUT + BN - 1) / BN, gy);
    gemm_pipe<true><<<gridF, 256, SMEM_BYTES>>>(hin, woc, out, NN, NOUT, NOUTP, FF, bout);
}

// round 17
// speedup vs baseline: 2.2961x; 1.4511x over previous
#include <cuda_runtime.h>
#include <cuda_fp16.h>
#include <math.h>
#include <stdint.h>

// Problem constants (fixed-shape problem)
#define NN 40000      // nodes
#define NE 150000     // edges per type
#define HH 4          // heads
#define DD 128        // per-head dim
#define FF 512        // HH*DD
#define FF2 1024      // both edge types concatenated
#define NOUT 2983
#define NOUTP 2984
#define SCB 157       // scan blocks: ceil(NN/256)

// ---------------------------------------------------------------------------
// Scratch (device globals; no allocation allowed)
// ---------------------------------------------------------------------------
__device__ float  g_feat[(size_t)NN * FF2];          // fp32 GEMM output
__device__ __half g_h1h [(size_t)NN * FF];
__device__ __half g_h2h [(size_t)NN * FF];
__device__ __half g_xh  [(size_t)NN * 1024];         // fp16 x
__device__ __half g_w0t [(size_t)FF2 * 1024];        // [n=1024][k=1024]
__device__ __half g_w1t [(size_t)FF2 * 512];         // [n=1024][k=512]
__device__ __half g_w2t [(size_t)FF2 * 512];
__device__ __half g_wot [(size_t)NOUTP * 512];       // [n][k], zero-padded
__device__ float  g_el  [2][NN * HH];
__device__ float  g_er  [2][NN * HH];
__device__ int    g_deg [NN];
__device__ int    g_cur [NN];
__device__ int    g_bsum[256];
__device__ int    g_rp  [2][NN + 1];
__device__ int    g_csrc[2][NE];

// ---------------------------------------------------------------------------
// Helpers
// ---------------------------------------------------------------------------
__device__ __forceinline__ void mma_f16(float c[4],
                                        uint32_t a0, uint32_t a1, uint32_t a2, uint32_t a3,
                                        uint32_t b0, uint32_t b1)
{
    asm volatile(
        "mma.sync.aligned.m16n8k16.row.col.f32.f16.f16.f32 "
        "{%0,%1,%2,%3}, {%4,%5,%6,%7}, {%8,%9}, {%0,%1,%2,%3};\n"
        : "+f"(c[0]), "+f"(c[1]), "+f"(c[2]), "+f"(c[3])
        : "r"(a0), "r"(a1), "r"(a2), "r"(a3), "r"(b0), "r"(b1));
}

__device__ __forceinline__ void cp_async16(uint32_t saddr, const void* gptr, int bytes)
{
    asm volatile("cp.async.cg.shared.global [%0], [%1], 16, %2;\n"
                 :: "r"(saddr), "l"(gptr), "r"(bytes));
}
__device__ __forceinline__ void cp_commit()
{
    asm volatile("cp.async.commit_group;\n");
}
__device__ __forceinline__ void cp_wait1()
{
    asm volatile("cp.async.wait_group 1;\n" ::: "memory");
}

// ---------------------------------------------------------------------------
// FP16 tensor-core GEMM (m16n8k16), cp.async 3-stage pipeline, 2 CTAs/SM.
// CTA tile 128x128, BK=64 halfs (128B rows), 256 threads, warp tile 64x32.
// C[M,Ncols] = A[M,K] @ Bt[N,K]^T  (A row-major half, Bt row-major half).
// Pitch 72 halfs: both fragment patterns bank-conflict-free (banks 4g+q).
// ---------------------------------------------------------------------------
#define BM 128
#define BN 128
#define BKH 64                                 // K per tile (halfs)
#define STAGES 3
#define LDH 72                                 // smem pitch in halfs
#define A_HALFS (BM * LDH)                     // 9216
#define B_HALFS (BN * LDH)                     // 9216
#define STG_HALFS (A_HALFS + B_HALFS)          // 18432
#define SMEM_BYTES (STAGES * STG_HALFS * 2)    // 110592 -> 2 CTAs/SM

extern __shared__ __half smem_h[];

template <bool ADD_BIAS>
__global__ __launch_bounds__(256, 2)
void gemm_pipe(const __half* __restrict__ A, const __half* __restrict__ Bt,
               float* __restrict__ C, int M, int Ncols, int NBrows, int K,
               const float* __restrict__ bias)
{
    const int tid  = threadIdx.x;
    const int wid  = tid >> 5;
    const int lane = tid & 31;
    const int wm   = wid & 1;          // 2 row groups x 64
    const int wn   = wid >> 1;         // 4 col groups x 32
    const int g    = lane >> 2;
    const int q    = lane & 3;

    const int bm = blockIdx.y * BM;
    const int bn = blockIdx.x * BN;

    const uint32_t sbase = (uint32_t)__cvta_generic_to_shared(smem_h);

    float c[4][4][4];
    #pragma unroll
    for (int i = 0; i < 4; i++)
        #pragma unroll
        for (int j = 0; j < 4; j++)
            #pragma unroll
            for (int r = 0; r < 4; r++) c[i][j][r] = 0.f;

    const int nt = K / BKH;

    auto load_stage = [&](int s, int t) {
        const int k0 = t * BKH;
        const uint32_t ss = sbase + (uint32_t)(s * STG_HALFS) * 2u;
        // A tile: 128 rows x 128B = 1024 chunks, 4/thread
        #pragma unroll
        for (int i = 0; i < 4; i++) {
            int f   = i * 256 + tid;
            int row = f >> 3;                 // 0..127
            int c16 = f & 7;                  // 16B chunk in row
            int m   = bm + row;
            const __half* ga = (m < M) ? (A + (size_t)m * K + k0 + c16 * 8) : A;
            cp_async16(ss + (uint32_t)(row * LDH + c16 * 8) * 2u, ga, (m < M) ? 16 : 0);
        }
        // B tile: 128 n-rows x 128B = 1024 chunks, 4/thread
        #pragma unroll
        for (int i = 0; i < 4; i++) {
            int f   = i * 256 + tid;
            int row = f >> 3;
            int c16 = f & 7;
            int n   = bn + row;
            const __half* gb = (n < NBrows) ? (Bt + (size_t)n * K + k0 + c16 * 8) : Bt;
            cp_async16(ss + (uint32_t)(A_HALFS + row * LDH + c16 * 8) * 2u, gb,
                       (n < NBrows) ? 16 : 0);
        }
        cp_commit();
    };

    #pragma unroll
    for (int s = 0; s < STAGES - 1; s++)
        load_stage(s, s);

    for (int t = 0; t < nt; t++) {
        cp_wait1();
        __syncthreads();

        const __half* As = smem_h + (t % STAGES) * STG_HALFS;
        const __half* Bs = As + A_HALFS;

        #pragma unroll
        for (int ks = 0; ks < 4; ks++) {
            const int kh = ks * 16;
            uint32_t a[4][4], b[4][2];
            #pragma unroll
            for (int mi = 0; mi < 4; mi++) {
                int r = wm * 64 + mi * 16 + g;
                a[mi][0] = *reinterpret_cast<const uint32_t*>(As + (r    ) * LDH + kh + 2 * q);
                a[mi][1] = *reinterpret_cast<const uint32_t*>(As + (r + 8) * LDH + kh + 2 * q);
                a[mi][2] = *reinterpret_cast<const uint32_t*>(As + (r    ) * LDH + kh + 2 * q + 8);
                a[mi][3] = *reinterpret_cast<const uint32_t*>(As + (r + 8) * LDH + kh + 2 * q + 8);
            }
            #pragma unroll
            for (int nj = 0; nj < 4; nj++) {
                int cn = wn * 32 + nj * 8 + g;
                b[nj][0] = *reinterpret_cast<const uint32_t*>(Bs + cn * LDH + kh + 2 * q);
                b[nj][1] = *reinterpret_cast<const uint32_t*>(Bs + cn * LDH + kh + 2 * q + 8);
            }
            #pragma unroll
            for (int mi = 0; mi < 4; mi++)
                #pragma unroll
                for (int nj = 0; nj < 4; nj++)
                    mma_f16(c[mi][nj], a[mi][0], a[mi][1], a[mi][2], a[mi][3],
                            b[nj][0], b[nj][1]);
        }

        if (t + STAGES - 1 < nt)
            load_stage((t + STAGES - 1) % STAGES, t + STAGES - 1);
        else
            cp_commit();
    }

    #pragma unroll
    for (int mi = 0; mi < 4; mi++) {
        int row0 = bm + wm * 64 + mi * 16 + g;
        #pragma unroll
        for (int nj = 0; nj < 4; nj++) {
            int col0 = bn + wn * 32 + nj * 8 + 2 * q;
            #pragma unroll
            for (int r = 0; r < 4; r++) {
                int row = row0 + (r >= 2 ? 8 : 0);
                int col = col0 + (r & 1);
                if (row < M && col < Ncols) {
                    float v = c[mi][nj][r];
                    if (ADD_BIAS) v += bias[col];
                    C[(size_t)row * Ncols + col] = v;
                }
            }
        }
    }
}

// ---------------------------------------------------------------------------
// Fused prep: x->half; W0..W2 transpose+concat->half [n][k]; Wout^T pad->half.
// ---------------------------------------------------------------------------
#define P0 (NN * 256)                  // float4s of x
#define P1 (FF2 * 1024)                // w0t
#define P2 (FF2 * 512)                 // w1t
#define P3 (FF2 * 512)                 // w2t
#define P4 (NOUTP * 512)               // wot
#define PTOT (P0 + P1 + P2 + P3 + P4)

__global__ void prep_all_kernel(const float* __restrict__ x, __half* __restrict__ xh,
                                const float* __restrict__ W0, __half* __restrict__ w0t,
                                const float* __restrict__ W1, __half* __restrict__ w1t,
                                const float* __restrict__ W2, __half* __restrict__ w2t,
                                const float* __restrict__ Wo, __half* __restrict__ wot)
{
    int i = blockIdx.x * blockDim.x + threadIdx.x;
    if (i >= PTOT) return;

    if (i < P0) {
        float4 v = reinterpret_cast<const float4*>(x)[i];
        __half2* o = reinterpret_cast<__half2*>(xh + (size_t)i * 4);
        o[0] = __floats2half2_rn(v.x, v.y);
        o[1] = __floats2half2_rn(v.z, v.w);
        return;
    }
    i -= P0;
    if (i < P1) {
        int n = i >> 10, k = i & 1023;
        int t = n >> 9, nn = n & 511;
        w0t[i] = __float2half_rn(W0[((size_t)t * 1024 + k) * 512 + nn]);
        return;
    }
    i -= P1;
    if (i < P2) {
        int n = i >> 9, k = i & 511;
        int t = n >> 9, nn = n & 511;
        w1t[i] = __float2half_rn(W1[((size_t)t * 512 + k) * 512 + nn]);
        return;
    }
    i -= P2;
    if (i < P3) {
        int n = i >> 9, k = i & 511;
        int t = n >> 9, nn = n & 511;
        w2t[i] = __float2half_rn(W2[((size_t)t * 512 + k) * 512 + nn]);
        return;
    }
    i -= P3;
    {
        int n = i >> 9, k = i & 511;
        wot[i] = (n < NOUT) ? __float2half_rn(Wo[(size_t)k * NOUT + n]) : __half(0.f);
    }
}

// ---------------------------------------------------------------------------
// CSR construction: histogram + two-level parallel scan + scatter
// ---------------------------------------------------------------------------
__global__ void hist_kernel(const int* __restrict__ dst, int* __restrict__ deg)
{
    int i = blockIdx.x * blockDim.x + threadIdx.x;
    if (i < NE) atomicAdd(&deg[dst[i]], 1);
}

__global__ __launch_bounds__(256)
void scan1_kernel(const int* __restrict__ deg, int* __restrict__ rp,
                  int* __restrict__ bsum)
{
    __shared__ int sm[256];
    int tid = threadIdx.x;
    int i = blockIdx.x * 256 + tid;
    int v = (i < NN) ? deg[i] : 0;
    sm[tid] = v;
    __syncthreads();
    #pragma unroll
    for (int off = 1; off < 256; off <<= 1) {
        int t = (tid >= off) ? sm[tid - off] : 0;
        __syncthreads();
        sm[tid] += t;
        __syncthreads();
    }
    if (i < NN) rp[i] = sm[tid] - v;
    if (tid == 255) bsum[blockIdx.x] = sm[255];
}

__global__ __launch_bounds__(256)
void scan2_kernel(int* __restrict__ bsum)
{
    __shared__ int sm[256];
    int tid = threadIdx.x;
    int v = (tid < SCB) ? bsum[tid] : 0;
    sm[tid] = v;
    __syncthreads();
    #pragma unroll
    for (int off = 1; off < 256; off <<= 1) {
        int t = (tid >= off) ? sm[tid - off] : 0;
        __syncthreads();
        sm[tid] += t;
        __syncthreads();
    }
    if (tid < SCB) bsum[tid] = sm[tid] - v;
}

__global__ __launch_bounds__(256)
void scan3_kernel(int* __restrict__ rp, int* __restrict__ cur,
                  const int* __restrict__ bsum)
{
    int i = blockIdx.x * 256 + threadIdx.x;
    if (i < NN) {
        int v = rp[i] + bsum[blockIdx.x];
        rp[i]  = v;
        cur[i] = v;
    }
    if (i == 0) rp[NN] = NE;
}

__global__ void scatter_kernel(const int* __restrict__ src, const int* __restrict__ dst,
                               int* __restrict__ cur, int* __restrict__ csrc)
{
    int i = blockIdx.x * blockDim.x + threadIdx.x;
    if (i < NE) {
        int p = atomicAdd(&cur[dst[i]], 1);
        csrc[p] = src[i];
    }
}

// ---------------------------------------------------------------------------
// Attention logits, BOTH edge types. One warp per (node, head).
// ---------------------------------------------------------------------------
__global__ void logits2_kernel(const float* __restrict__ feat,
                               const float* __restrict__ al,
                               const float* __restrict__ ar,
                               float* __restrict__ el, float* __restrict__ er)
{
    int gw   = (blockIdx.x * blockDim.x + threadIdx.x) >> 5;
    int lane = threadIdx.x & 31;
    if (gw >= NN * HH) return;
    int n = gw >> 2;
    int h = gw & 3;

    #pragma unroll
    for (int t = 0; t < 2; t++) {
        float4 fv = reinterpret_cast<const float4*>(feat + (size_t)n * FF2 + t * FF + h * DD)[lane];
        float4 av = reinterpret_cast<const float4*>(al + t * FF + h * DD)[lane];
        float4 rv = reinterpret_cast<const float4*>(ar + t * FF + h * DD)[lane];

        float dl = fv.x * av.x + fv.y * av.y + fv.z * av.z + fv.w * av.w;
        float dr = fv.x * rv.x + fv.y * rv.y + fv.z * rv.z + fv.w * rv.w;
        #pragma unroll
        for (int o = 16; o; o >>= 1) {
            dl += __shfl_xor_sync(0xFFFFFFFFu, dl, o);
            dr += __shfl_xor_sync(0xFFFFFFFFu, dr, o);
        }
        if (lane == 0) {
            el[t * (NN * HH) + gw] = dl;
            er[t * (NN * HH) + gw] = dr;
        }
    }
}

// ---------------------------------------------------------------------------
// Fused aggregation, BOTH edge types; output stored as fp16 (next GEMM input).
// ---------------------------------------------------------------------------
__global__ __launch_bounds__(256)
void aggr2_kernel(const int* __restrict__ rp0, const int* __restrict__ cs0,
                  const int* __restrict__ rp1, const int* __restrict__ cs1,
                  const float* __restrict__ el, const float* __restrict__ er,
                  const float* __restrict__ feat, const float* __restrict__ bias,
                  __half* __restrict__ hout, int activate)
{
    int gw   = (blockIdx.x * blockDim.x + threadIdx.x) >> 5;
    int lane = threadIdx.x & 31;
    if (gw >= NN * HH) return;
    int n = gw >> 2;
    int h = gw & 3;

    float4 out4 = make_float4(0.f, 0.f, 0.f, 0.f);

    #pragma unroll
    for (int t = 0; t < 2; t++) {
        const int* rp = t ? rp1 : rp0;
        const int* cs = t ? cs1 : cs0;
        const float* elt = el + t * (NN * HH);
        float erd = er[t * (NN * HH) + gw];
        const float* ft = feat + t * FF;

        int beg = rp[n];
        int end = rp[n + 1];

        float mx = -INFINITY;
        for (int i = beg + lane; i < end; i += 32) {
            int s = cs[i];
            float v = elt[s * HH + h] + erd;
            v = (v > 0.f) ? v : 0.2f * v;
            mx = fmaxf(mx, v);
        }
        #pragma unroll
        for (int o = 16; o; o >>= 1)
            mx = fmaxf(mx, __shfl_xor_sync(0xFFFFFFFFu, mx, o));

        float ss = 0.f;
        for (int i = beg + lane; i < end; i += 32) {
            int s = cs[i];
            float v = elt[s * HH + h] + erd;
            v = (v > 0.f) ? v : 0.2f * v;
            ss += __expf(v - mx);
        }
        #pragma unroll
        for (int o = 16; o; o >>= 1)
            ss += __shfl_xor_sync(0xFFFFFFFFu, ss, o);
        float inv = (end > beg) ? 1.f / ss : 0.f;

        float4 acc = make_float4(0.f, 0.f, 0.f, 0.f);
        for (int i = beg; i < end; i++) {
            int s = cs[i];
            float v = elt[s * HH + h] + erd;
            v = (v > 0.f) ? v : 0.2f * v;
            float a = __expf(v - mx) * inv;
            float4 fv = reinterpret_cast<const float4*>(ft + (size_t)s * FF2 + h * DD)[lane];
            acc.x = fmaf(a, fv.x, acc.x);
            acc.y = fmaf(a, fv.y, acc.y);
            acc.z = fmaf(a, fv.z, acc.z);
            acc.w = fmaf(a, fv.w, acc.w);
        }

        float4 b4 = reinterpret_cast<const float4*>(bias + t * FF + h * DD)[lane];
        float o0 = acc.x + b4.x, o1 = acc.y + b4.y;
        float o2 = acc.z + b4.z, o3 = acc.w + b4.w;
        if (activate) {
            o0 = (o0 > 0.f) ? o0 : 0.01f * o0;
            o1 = (o1 > 0.f) ? o1 : 0.01f * o1;
            o2 = (o2 > 0.f) ? o2 : 0.01f * o2;
            o3 = (o3 > 0.f) ? o3 : 0.01f * o3;
        }
        out4.x += o0; out4.y += o1; out4.z += o2; out4.w += o3;
    }

    size_t off = (size_t)n * FF + h * DD + lane * 4;
    __half2* op = reinterpret_cast<__half2*>(hout + off);
    op[0] = __floats2half2_rn(out4.x, out4.y);
    op[1] = __floats2half2_rn(out4.z, out4.w);
}

// ---------------------------------------------------------------------------
// Launch (single stream)
// ---------------------------------------------------------------------------
extern "C" void kernel_launch(void* const* d_in, const int* in_sizes, int n_in,
                              void* d_out, int out_size)
{
    const float* x = (const float*)d_in[0];
    const int* src[2] = {(const int*)d_in[1], (const int*)d_in[3]};
    const int* dst[2] = {(const int*)d_in[2], (const int*)d_in[4]};
    const float* W [3] = {(const float*)d_in[5],  (const float*)d_in[9],  (const float*)d_in[13]};
    const float* al[3] = {(const float*)d_in[6],  (const float*)d_in[10], (const float*)d_in[14]};
    const float* ar[3] = {(const float*)d_in[7],  (const float*)d_in[11], (const float*)d_in[15]};
    const float* bb[3] = {(const float*)d_in[8],  (const float*)d_in[12], (const float*)d_in[16]};
    const float* Wout = (const float*)d_in[17];
    const float* bout = (const float*)d_in[18];
    float* out = (float*)d_out;

    float *feat, *el2, *er2;
    __half *h1h, *h2h, *xh, *w0t, *w1t, *w2t, *wot;
    int *deg, *cur, *bsum, *rp, *csrc;
    cudaGetSymbolAddress((void**)&feat, g_feat);
    cudaGetSymbolAddress((void**)&h1h,  g_h1h);
    cudaGetSymbolAddress((void**)&h2h,  g_h2h);
    cudaGetSymbolAddress((void**)&xh,   g_xh);
    cudaGetSymbolAddress((void**)&w0t,  g_w0t);
    cudaGetSymbolAddress((void**)&w1t,  g_w1t);
    cudaGetSymbolAddress((void**)&w2t,  g_w2t);
    cudaGetSymbolAddress((void**)&wot,  g_wot);
    cudaGetSymbolAddress((void**)&el2,  g_el);
    cudaGetSymbolAddress((void**)&er2,  g_er);
    cudaGetSymbolAddress((void**)&deg,  g_deg);
    cudaGetSymbolAddress((void**)&cur,  g_cur);
    cudaGetSymbolAddress((void**)&bsum, g_bsum);
    cudaGetSymbolAddress((void**)&rp,   g_rp);
    cudaGetSymbolAddress((void**)&csrc, g_csrc);

    static bool init_done = false;
    if (!init_done) {
        cudaFuncSetAttribute(gemm_pipe<false>, cudaFuncAttributeMaxDynamicSharedMemorySize, SMEM_BYTES);
        cudaFuncSetAttribute(gemm_pipe<true>,  cudaFuncAttributeMaxDynamicSharedMemorySize, SMEM_BYTES);
        init_done = true;
    }

    const int neBlocks = (NE + 255) / 256;
    const int lgBlocks = (NN * HH * 32 + 255) / 256;
    const int agBlocks = (NN * HH + 7) / 8;
    const int gy = (NN + BM - 1) / BM;   // 313

    const __half* Wc[3] = {w0t, w1t, w2t};
    const int Ks[3] = {1024, 512, 512};
    __half* houts[3] = {h1h, h2h, h1h};

    // ---- single fused prep launch ----
    prep_all_kernel<<<(PTOT + 255) / 256, 256>>>(x, xh, W[0], w0t, W[1], w1t,
                                                 W[2], w2t, Wout, wot);

    // ---- Layer 0 GEMM ----
    {
        dim3 grid(FF2 / BN, gy);
        gemm_pipe<false><<<grid, 256, SMEM_BYTES>>>(xh, Wc[0], feat, NN, FF2, FF2, Ks[0], nullptr);
    }

    // ---- CSR for both edge types ----
    for (int t = 0; t < 2; t++) {
        int* rpt = rp + t * (NN + 1);
        int* cst = csrc + t * NE;
        cudaMemsetAsync(deg, 0, NN * sizeof(int), 0);
        hist_kernel<<<neBlocks, 256>>>(dst[t], deg);
        scan1_kernel<<<SCB, 256>>>(deg, rpt, bsum);
        scan2_kernel<<<1, 256>>>(bsum);
        scan3_kernel<<<SCB, 256>>>(rpt, cur, bsum);
        scatter_kernel<<<neBlocks, 256>>>(src[t], dst[t], cur, cst);
    }

    const __half* hin = xh;
    for (int L = 0; L < 3; L++) {
        __half* hout = houts[L];
        if (L > 0) {
            dim3 grid(FF2 / BN, gy);
            gemm_pipe<false><<<grid, 256, SMEM_BYTES>>>(hin, Wc[L], feat, NN, FF2, FF2, Ks[L], nullptr);
        }
        logits2_kernel<<<lgBlocks, 256>>>(feat, al[L], ar[L], el2, er2);
        aggr2_kernel<<<agBlocks, 256>>>(rp, csrc, rp + (NN + 1), csrc + NE,
                                        el2, er2, feat, bb[L], hout,
                                        (L < 2) ? 1 : 0);
        hin = hout;
    }

    dim3 gridF((NOUT + BN - 1) / BN, gy);
    gemm_pipe<true><<<gridF, 256, SMEM_BYTES>>>(hin, wot, out, NN, NOUT, NOUTP, FF, bout);
}